// round 4
// baseline (speedup 1.0000x reference)
#include <cuda_runtime.h>
#include <cstdint>

// out[i] = x[i] + 42.0f, 8192*4096 fp32. HBM-bound stream at ~7.1 TB/s effective.
// This round: 256-bit vector ld/st (sm_100+ PTX .v8.f32) for 1KB/warp bursts.

constexpr int TPB = 256;
constexpr int U8  = 4;                 // float8 (32B) per thread
constexpr int TILE8 = TPB * U8;        // float8 per block = 1024 (32KB/block)

__device__ __forceinline__ void ld_v8_cs(const float* p, float4& a, float4& b) {
    asm volatile("ld.global.cs.v8.f32 {%0,%1,%2,%3,%4,%5,%6,%7}, [%8];"
        : "=f"(a.x), "=f"(a.y), "=f"(a.z), "=f"(a.w),
          "=f"(b.x), "=f"(b.y), "=f"(b.z), "=f"(b.w)
        : "l"(p));
}

__device__ __forceinline__ void st_v8_cs(float* p, const float4& a, const float4& b) {
    asm volatile("st.global.cs.v8.f32 [%0], {%1,%2,%3,%4,%5,%6,%7,%8};"
        :: "l"(p),
           "f"(a.x), "f"(a.y), "f"(a.z), "f"(a.w),
           "f"(b.x), "f"(b.y), "f"(b.z), "f"(b.w)
        : "memory");
}

__global__ void __launch_bounds__(TPB) add42_v8(const float* __restrict__ in,
                                                float* __restrict__ out) {
    // index in float8 (32B) units
    const unsigned base8 = blockIdx.x * TILE8 + threadIdx.x;
    float4 a[U8], b[U8];
    #pragma unroll
    for (int k = 0; k < U8; k++)
        ld_v8_cs(in + (size_t)(base8 + k * TPB) * 8, a[k], b[k]);
    #pragma unroll
    for (int k = 0; k < U8; k++) {
        a[k].x += 42.0f; a[k].y += 42.0f; a[k].z += 42.0f; a[k].w += 42.0f;
        b[k].x += 42.0f; b[k].y += 42.0f; b[k].z += 42.0f; b[k].w += 42.0f;
        st_v8_cs(out + (size_t)(base8 + k * TPB) * 8, a[k], b[k]);
    }
}

// Grid-stride float4 fallback for any remainder after exact 32KB tiles.
__global__ void __launch_bounds__(TPB) add42_vec4_gs(const float4* __restrict__ in,
                                                     float4* __restrict__ out,
                                                     long long start, long long n4) {
    const long long stride = (long long)gridDim.x * blockDim.x;
    for (long long i = start + (long long)blockIdx.x * blockDim.x + threadIdx.x;
         i < n4; i += stride) {
        float4 v = __ldcs(&in[i]);
        v.x += 42.0f; v.y += 42.0f; v.z += 42.0f; v.w += 42.0f;
        __stcs(&out[i], v);
    }
}

__global__ void add42_tail(const float* __restrict__ in, float* __restrict__ out,
                           long long start, long long n) {
    long long i = start + (long long)blockIdx.x * blockDim.x + threadIdx.x;
    if (i < n) out[i] = in[i] + 42.0f;
}

extern "C" void kernel_launch(void* const* d_in, const int* in_sizes, int n_in,
                              void* d_out, int out_size) {
    const float* x = (const float*)d_in[0];
    float* out = (float*)d_out;
    const long long n = (long long)in_sizes[0];

    const long long n8 = n / 8;
    const long long exact_blocks = n8 / TILE8;        // 4096 for 8192x4096
    if (exact_blocks > 0) {
        add42_v8<<<(int)exact_blocks, TPB>>>(x, out);
    }
    // Remainder in float4 units
    const long long done4 = exact_blocks * (long long)TILE8 * 2;  // float4 consumed
    const long long n4 = n / 4;
    if (done4 < n4) {
        long long rem = n4 - done4;
        int blocks = (int)((rem + TPB - 1) / TPB);
        if (blocks > 152 * 8) blocks = 152 * 8;
        add42_vec4_gs<<<blocks, TPB>>>((const float4*)x, (float4*)out, done4, n4);
    }
    const long long tail_start = n4 * 4;
    if (tail_start < n) {
        long long tail = n - tail_start;
        int blocks = (int)((tail + 127) / 128);
        add42_tail<<<blocks, 128>>>(x, out, tail_start, n);
    }
}